// round 2
// baseline (speedup 1.0000x reference)
#include <cuda_runtime.h>
#include <cstdint>

#define BATCH 64
#define DIM   256
#define HW    1024
#define NPIX  65536      // BATCH * HW
#define NCODE 1024
#define TM    128        // pixels per block
#define TN    128        // codes per n-iteration
#define KC    32         // k-chunk

__device__ float g_bias[NCODE];   // sum(e_n^2), fp64-accumulated then fp32
__device__ int   g_idx[NPIX];     // argmin indices (scratch for gather)

// ---------------------------------------------------------------------------
// Kernel 1: per-code B_n = sum(emb[n]^2), accumulated in fp64 -> fp32
// ---------------------------------------------------------------------------
__global__ void vq_bias(const float* __restrict__ emb) {
    int n = blockIdx.x * blockDim.x + threadIdx.x;
    if (n < NCODE) {
        const float4* row = reinterpret_cast<const float4*>(emb + (size_t)n * DIM);
        double s = 0.0;
#pragma unroll
        for (int i = 0; i < DIM / 4; ++i) {
            float4 v = row[i];
            s += (double)v.x * v.x + (double)v.y * v.y
               + (double)v.z * v.z + (double)v.w * v.w;
        }
        g_bias[n] = (float)s;
    }
}

// ---------------------------------------------------------------------------
// Kernel 2: fused GEMM + quantization-faithful argmin.
// Reference computes d = fl32( fl32(||z||^2 + ||e||^2) - 2*dot ) at magnitude
// ~256 (ulp ~3e-5). We replicate that rounding structure exactly, with A, B
// accumulated in fp64 and dot from an fp32-FMA chain (err ~2e-6 << ulp), so
// ties and near-ties resolve the same way as the reference (lowest index).
// Block: 256 threads, 8x8 register tile -> 128 pixels x 128 codes per n-iter.
// ---------------------------------------------------------------------------
extern __shared__ float smem[];

__global__ __launch_bounds__(256, 1)
void vq_argmax(const float* __restrict__ z, const float* __restrict__ emb,
               float* __restrict__ fo, int* __restrict__ io) {
    float* zs = smem;                    // [DIM][TM]   128 KB
    float* es = smem + DIM * TM;         // [KC][TN]     16 KB
    float* As = smem + DIM * TM + KC * TN;  // [TM]      512 B

    const int t  = threadIdx.x;
    const int tx = t & 15;
    const int ty = t >> 4;
    const int b  = blockIdx.x >> 3;           // batch
    const int q0 = (blockIdx.x & 7) * TM;     // pixel offset within HW plane

    // ---- load z tile: z[b, k, q0+m] contiguous in m -> coalesced ----
    {
        const float* zb = z + (size_t)b * DIM * HW + q0;
        int m4 = (t & 31) * 4;
        int k0 = t >> 5;
#pragma unroll
        for (int i = 0; i < 32; ++i) {
            int k = k0 + i * 8;
            float4 v = *reinterpret_cast<const float4*>(zb + (size_t)k * HW + m4);
            *reinterpret_cast<float4*>(&zs[k * TM + m4]) = v;
        }
    }
    __syncthreads();

    // ---- A_m = sum_k z[m,k]^2 in fp64 -> fp32 (threads 0..127, 1 pixel each)
    if (t < TM) {
        double s = 0.0;
#pragma unroll 8
        for (int k = 0; k < DIM; ++k) {
            float v = zs[k * TM + t];
            s += (double)v * v;
        }
        As[t] = (float)s;
    }
    __syncthreads();

    float Av[8];
#pragma unroll
    for (int i = 0; i < 8; ++i) Av[i] = As[ty * 4 + (i < 4 ? i : 60 + i)];

    float best[8];
    int   bidx[8];
#pragma unroll
    for (int i = 0; i < 8; ++i) { best[i] = 3.4e38f; bidx[i] = 0; }

    for (int nt = 0; nt < NCODE / TN; ++nt) {
        const int nbase = nt * TN;
        float acc[8][8];
#pragma unroll
        for (int i = 0; i < 8; ++i)
#pragma unroll
            for (int j = 0; j < 8; ++j) acc[i][j] = 0.f;

        for (int kc = 0; kc < DIM / KC; ++kc) {
            __syncthreads();
            {   // stage emb chunk: es[k][n] = emb[nbase+n][kc*KC + k]
                int n    = t & 127;
                int half = t >> 7;
                const float4* src = reinterpret_cast<const float4*>(
                    emb + (size_t)(nbase + n) * DIM + kc * KC + half * 16);
#pragma unroll
                for (int j = 0; j < 4; ++j) {
                    float4 v = src[j];
                    int kl = half * 16 + j * 4;
                    es[(kl + 0) * TN + n] = v.x;
                    es[(kl + 1) * TN + n] = v.y;
                    es[(kl + 2) * TN + n] = v.z;
                    es[(kl + 3) * TN + n] = v.w;
                }
            }
            __syncthreads();

#pragma unroll 8
            for (int k = 0; k < KC; ++k) {
                const float* zr = &zs[(kc * KC + k) * TM];
                const float* er = &es[k * TN];
                float4 a0 = *reinterpret_cast<const float4*>(zr + ty * 4);
                float4 a1 = *reinterpret_cast<const float4*>(zr + ty * 4 + 64);
                float4 b0 = *reinterpret_cast<const float4*>(er + tx * 4);
                float4 b1 = *reinterpret_cast<const float4*>(er + tx * 4 + 64);
                float av[8] = {a0.x, a0.y, a0.z, a0.w, a1.x, a1.y, a1.z, a1.w};
                float bv[8] = {b0.x, b0.y, b0.z, b0.w, b1.x, b1.y, b1.z, b1.w};
#pragma unroll
                for (int i = 0; i < 8; ++i)
#pragma unroll
                    for (int j = 0; j < 8; ++j)
                        acc[i][j] = __fmaf_rn(av[i], bv[j], acc[i][j]);
            }
        }

        // quantization-faithful distance + argmin (ascending n, strict '<'
        // keeps the lowest index on exact ties, matching jnp.argmin)
#pragma unroll
        for (int j = 0; j < 8; ++j) {
            int n = nbase + tx * 4 + (j < 4 ? j : 60 + j);
            float Bn = __ldg(&g_bias[n]);
#pragma unroll
            for (int i = 0; i < 8; ++i) {
                float d = __fadd_rn(__fadd_rn(Av[i], Bn), -2.0f * acc[i][j]);
                if (d < best[i]) { best[i] = d; bidx[i] = n; }
            }
        }
    }

    // cross-thread argmin: 16 threads sharing ty form one half-warp
#pragma unroll
    for (int i = 0; i < 8; ++i) {
        float bv = best[i];
        int   bi = bidx[i];
#pragma unroll
        for (int off = 1; off < 16; off <<= 1) {
            float ov = __shfl_xor_sync(0xffffffffu, bv, off);
            int   oi = __shfl_xor_sync(0xffffffffu, bi, off);
            if (ov < bv || (ov == bv && oi < bi)) { bv = ov; bi = oi; }
        }
        if (tx == 0) {
            int m = ty * 4 + (i < 4 ? i : 60 + i);
            int p = b * HW + q0 + m;
            g_idx[p] = bi;
            if (fo) fo[p] = (float)bi;
            if (io) io[p] = bi;
        }
    }
}

// ---------------------------------------------------------------------------
// Kernel 3: z_q gather. out[b, d, h, w] = emb[idx[b,h,w], d].
// ---------------------------------------------------------------------------
__global__ void vq_gather(const float* __restrict__ emb, float* __restrict__ zq) {
    int p = blockIdx.x * blockDim.x + threadIdx.x;
    int b = p >> 10;
    int q = p & 1023;
    int idx = g_idx[p];
    const float4* row = reinterpret_cast<const float4*>(emb + (size_t)idx * DIM);
    float* o = zq + (size_t)b * DIM * HW + q;
#pragma unroll 8
    for (int i = 0; i < DIM / 4; ++i) {
        float4 v = row[i];
        o[(size_t)(4 * i + 0) * HW] = v.x;
        o[(size_t)(4 * i + 1) * HW] = v.y;
        o[(size_t)(4 * i + 2) * HW] = v.z;
        o[(size_t)(4 * i + 3) * HW] = v.w;
    }
}

// ---------------------------------------------------------------------------
extern "C" void kernel_launch(void* const* d_in, const int* in_sizes, int n_in,
                              void* d_out, int out_size) {
    const float* z   = (const float*)d_in[0];
    const float* emb = (const float*)d_in[1];
    if (n_in >= 2 && in_sizes[0] == NCODE * DIM) {
        emb = (const float*)d_in[0];
        z   = (const float*)d_in[1];
    } else if (n_in >= 2 && in_sizes[1] == NCODE * DIM) {
        z   = (const float*)d_in[0];
        emb = (const float*)d_in[1];
    }

    const int ZQ = NPIX * DIM;  // 16777216
    float* fo = nullptr;
    int*   io = nullptr;
    float* zq = nullptr;

    if (out_size == NPIX) {
        io = (int*)d_out;                       // indices only
    } else if (out_size == ZQ) {
        zq = (float*)d_out;                     // z_q only
    } else {
        fo = (float*)d_out;                     // [indices | z_q] concat
        zq = (float*)d_out + NPIX;
    }

    const int SMEM_BYTES = (DIM * TM + KC * TN + TM) * (int)sizeof(float);
    cudaFuncSetAttribute(vq_argmax, cudaFuncAttributeMaxDynamicSharedMemorySize,
                         SMEM_BYTES);

    vq_bias<<<(NCODE + 255) / 256, 256>>>(emb);
    vq_argmax<<<NPIX / TM, 256, SMEM_BYTES>>>(z, emb, fo, io);
    if (zq) vq_gather<<<NPIX / 256, 256>>>(emb, zq);
}

// round 5
// speedup vs baseline: 1.8850x; 1.8850x over previous
#include <cuda_runtime.h>
#include <cuda_bf16.h>
#include <cstdint>

#define DIM    256
#define HW     1024
#define NPIX   65536
#define NCODE  1024
#define NCHUNK 8          // 1024 codes / 128 per chunk

// ------------------------- device globals (scratch) -------------------------
__device__ float         g_bias[NCODE];        // sum(e_n^2), fp64->fp32
__device__ float         g_A[NPIX];            // sum(z_p^2), fp64->fp32
__device__ int           g_cand[NPIX * 8];     // top-8 approx candidates
__device__ int           g_idx[NPIX];          // final indices
__device__ __nv_bfloat16 g_embh[NCODE * DIM];  // bf16 codebook

// ------------------------- PTX helpers (baseline ISA only) ------------------
__device__ __forceinline__ uint32_t smem_u32(const void* p) {
    uint32_t a;
    asm("{ .reg .u64 t; cvta.to.shared.u64 t, %1; cvt.u32.u64 %0, t; }"
        : "=r"(a) : "l"(p));
    return a;
}
__device__ __forceinline__ void ldsm4(uint32_t& r0, uint32_t& r1, uint32_t& r2,
                                      uint32_t& r3, uint32_t addr) {
    asm volatile("ldmatrix.sync.aligned.m8n8.x4.shared.b16 {%0,%1,%2,%3}, [%4];"
                 : "=r"(r0), "=r"(r1), "=r"(r2), "=r"(r3) : "r"(addr));
}
__device__ __forceinline__ void mma16816(float* d, const uint32_t* a,
                                         uint32_t b0, uint32_t b1) {
    asm volatile("mma.sync.aligned.m16n8k16.row.col.f32.bf16.bf16.f32 "
                 "{%0,%1,%2,%3}, {%4,%5,%6,%7}, {%8,%9}, {%0,%1,%2,%3};"
                 : "+f"(d[0]), "+f"(d[1]), "+f"(d[2]), "+f"(d[3])
                 : "r"(a[0]), "r"(a[1]), "r"(a[2]), "r"(a[3]), "r"(b0), "r"(b1));
}
#define CP_ASYNC16(dst, src) \
    asm volatile("cp.async.cg.shared.global [%0], [%1], 16;" :: "r"(dst), "l"(src))
#define CP_COMMIT() asm volatile("cp.async.commit_group;" ::: "memory")
#define CP_WAIT0()  asm volatile("cp.async.wait_group 0;" ::: "memory")

// ---------------------------------------------------------------------------
// Kernel 1 (prep): g_bias (fp64 exact) + bf16 codebook. grid=32, block=256.
// ---------------------------------------------------------------------------
__global__ void vq_prep(const float* __restrict__ emb) {
    int w   = blockIdx.x * 8 + (threadIdx.x >> 5);
    int lid = threadIdx.x & 31;
#pragma unroll
    for (int i = 0; i < 4; ++i) {
        int n = w * 4 + i;
        const float4* row = reinterpret_cast<const float4*>(emb + (size_t)n * DIM);
        float4 u = __ldg(row + lid * 2);
        float4 t = __ldg(row + lid * 2 + 1);
        double s = (double)u.x * u.x + (double)u.y * u.y + (double)u.z * u.z + (double)u.w * u.w
                 + (double)t.x * t.x + (double)t.y * t.y + (double)t.z * t.z + (double)t.w * t.w;
#pragma unroll
        for (int off = 16; off; off >>= 1) s += __shfl_xor_sync(0xffffffffu, s, off);
        if (lid == 0) g_bias[n] = (float)s;
        __nv_bfloat162 h0 = __floats2bfloat162_rn(u.x, u.y);
        __nv_bfloat162 h1 = __floats2bfloat162_rn(u.z, u.w);
        __nv_bfloat162 h2 = __floats2bfloat162_rn(t.x, t.y);
        __nv_bfloat162 h3 = __floats2bfloat162_rn(t.z, t.w);
        uint4 o;
        o.x = *reinterpret_cast<uint32_t*>(&h0); o.y = *reinterpret_cast<uint32_t*>(&h1);
        o.z = *reinterpret_cast<uint32_t*>(&h2); o.w = *reinterpret_cast<uint32_t*>(&h3);
        *reinterpret_cast<uint4*>(&g_embh[(size_t)n * DIM + lid * 8]) = o;
    }
}

// ---------------------------------------------------------------------------
// Kernel 2: bf16 mma.sync GEMM + top-8 shortlist.
//   A: 128 pixels x 256 dims, resident smem (XOR swizzle, 512B rows)
//   B: 128-code chunks, cp.async double buffer
//   warps: 4 (M) x 2 (N); each warp 32x64 via 2x8 m16n8k16 tiles
// ---------------------------------------------------------------------------
#define SM_A   0
#define SM_B0  65536
#define SM_B1  131072
#define SM_AP  196608                 // double[256]
#define SM_TOT (196608 + 2048)

// smem byte offset for element (row, kchunk-of-8) in a 512B-row tile
#define ROWOFF(row, kc) ((row) * 512 + (((kc) ^ ((row) & 7)) << 4))

// prefetch one 128x256-bf16 chunk of the codebook into swizzled smem
__device__ __forceinline__ void prefetch_b(uint32_t bbuf, int nbase, int t) {
    const char* src = (const char*)g_embh + (size_t)nbase * 512;
#pragma unroll
    for (int i = 0; i < 16; ++i) {
        int idx = t + i * 256;       // 0..4095
        int n = idx >> 5, c = idx & 31;
        CP_ASYNC16(bbuf + ROWOFF(n, c), src + n * 512 + c * 16);
    }
}

extern __shared__ char smem[];

__global__ __launch_bounds__(256, 1)
void vq_gemm(const float* __restrict__ z) {
    const uint32_t sb = smem_u32(smem);
    const int t = threadIdx.x, wid = t >> 5, lane = t & 31;
    const int wm = wid & 3, wn = wid >> 2;
    const int b = blockIdx.x >> 3, q0 = (blockIdx.x & 7) * 128;

    // ---- stage A (fp32 -> bf16, swizzled) + fp64 ||z||^2 partials ----
    {
        const int m = t & 127, kh = t >> 7;
        const float* zb = z + (size_t)b * DIM * HW + q0 + m;
        double s = 0.0;
#pragma unroll 2
        for (int ch = 0; ch < 16; ++ch) {
            int k0 = kh * 128 + ch * 8;
            float vv[8];
#pragma unroll
            for (int j = 0; j < 8; ++j) {
                vv[j] = zb[(size_t)(k0 + j) * HW];
                s += (double)vv[j] * vv[j];
            }
            uint4 w;
            __nv_bfloat162 h0 = __floats2bfloat162_rn(vv[0], vv[1]);
            __nv_bfloat162 h1 = __floats2bfloat162_rn(vv[2], vv[3]);
            __nv_bfloat162 h2 = __floats2bfloat162_rn(vv[4], vv[5]);
            __nv_bfloat162 h3 = __floats2bfloat162_rn(vv[6], vv[7]);
            w.x = *reinterpret_cast<uint32_t*>(&h0); w.y = *reinterpret_cast<uint32_t*>(&h1);
            w.z = *reinterpret_cast<uint32_t*>(&h2); w.w = *reinterpret_cast<uint32_t*>(&h3);
            *reinterpret_cast<uint4*>(smem + SM_A + ROWOFF(m, k0 >> 3)) = w;
        }
        reinterpret_cast<double*>(smem + SM_AP)[t] = s;
    }

    // ---- prefetch B chunk 0 ----
    prefetch_b(sb + SM_B0, 0, t);
    CP_COMMIT();
    CP_WAIT0();
    __syncthreads();

    if (t < 128) {
        const double* ap = reinterpret_cast<const double*>(smem + SM_AP);
        g_A[b * HW + q0 + t] = (float)(ap[t] + ap[t + 128]);
    }

    // per-lane ldmatrix row geometry (x4: lanes 0-7 m0k0, 8-15 m8k0, 16-23 m0k8, 24-31 m8k8)
    const int lrow  = (lane & 7) + ((lane >> 3) & 1) * 8;
    const int kcsel = lane >> 4;
    const int rowA0 = wm * 32 + lrow;          // mt=0 (mt=1: +16)
    const int rowB0 = wn * 64 + lrow;          // g=0  (g: +16 each)

    // per-thread-row top-4 candidates (4 rows: mt*2 + h)
    float cv[4][4]; int ci[4][4]; float cmax[4]; int csl[4];
#pragma unroll
    for (int r = 0; r < 4; ++r) {
        cmax[r] = 3.4e38f; csl[r] = 0;
#pragma unroll
        for (int j = 0; j < 4; ++j) { cv[r][j] = 3.4e38f; ci[r][j] = 0; }
    }

    for (int nt = 0; nt < NCHUNK; ++nt) {
        if (nt + 1 < NCHUNK) {
            prefetch_b(sb + (((nt + 1) & 1) ? SM_B1 : SM_B0), (nt + 1) * 128, t);
            CP_COMMIT();
        }
        const uint32_t bbuf = sb + ((nt & 1) ? SM_B1 : SM_B0);

        float acc[2][8][4];
#pragma unroll
        for (int mt = 0; mt < 2; ++mt)
#pragma unroll
            for (int n2 = 0; n2 < 8; ++n2)
#pragma unroll
                for (int j = 0; j < 4; ++j) acc[mt][n2][j] = 0.f;

#pragma unroll
        for (int ks = 0; ks < 16; ++ks) {
            const int kc = 2 * ks + kcsel;
            uint32_t a[2][4];
#pragma unroll
            for (int mt = 0; mt < 2; ++mt) {
                int row = rowA0 + mt * 16;
                ldsm4(a[mt][0], a[mt][1], a[mt][2], a[mt][3],
                      sb + SM_A + ROWOFF(row, kc));
            }
#pragma unroll
            for (int g = 0; g < 4; ++g) {
                uint32_t r0, r1, r2, r3;
                int row = rowB0 + g * 16;
                ldsm4(r0, r1, r2, r3, bbuf + ROWOFF(row, kc));
#pragma unroll
                for (int mt = 0; mt < 2; ++mt) {
                    mma16816(acc[mt][g * 2 + 0], a[mt], r0, r2);
                    mma16816(acc[mt][g * 2 + 1], a[mt], r1, r3);
                }
            }
        }

        // ---- epilogue: s = bias - 2*dot, per-row top-4 insert ----
        const int nb0 = nt * 128 + wn * 64 + (lane & 3) * 2;
        float bias2[16];
#pragma unroll
        for (int n2 = 0; n2 < 8; ++n2) {
            bias2[n2 * 2 + 0] = __ldg(&g_bias[nb0 + n2 * 8 + 0]);
            bias2[n2 * 2 + 1] = __ldg(&g_bias[nb0 + n2 * 8 + 1]);
        }
#pragma unroll
        for (int mt = 0; mt < 2; ++mt)
#pragma unroll
            for (int h = 0; h < 2; ++h) {
                const int rr = mt * 2 + h;
#pragma unroll
                for (int n2 = 0; n2 < 8; ++n2)
#pragma unroll
                    for (int bb = 0; bb < 2; ++bb) {
                        float s2 = fmaf(-2.f, acc[mt][n2][h * 2 + bb], bias2[n2 * 2 + bb]);
                        if (s2 < cmax[rr]) {
                            cv[rr][csl[rr]] = s2;
                            ci[rr][csl[rr]] = nb0 + n2 * 8 + bb;
                            cmax[rr] = cv[rr][0]; csl[rr] = 0;
#pragma unroll
                            for (int u = 1; u < 4; ++u)
                                if (cv[rr][u] > cmax[rr]) { cmax[rr] = cv[rr][u]; csl[rr] = u; }
                        }
                    }
            }

        CP_WAIT0();
        __syncthreads();
    }

    // ---- merge 32 candidates/pixel -> top-8 (reuse B0 region as scratch) ----
    float* mv = reinterpret_cast<float*>(smem + SM_B0);
    int*   mi = reinterpret_cast<int*>(smem + SM_B0 + 128 * 32 * 4);
    const int owner = wn * 4 + (lane & 3);
#pragma unroll
    for (int rr = 0; rr < 4; ++rr) {
        int m = wm * 32 + (rr >> 1) * 16 + (rr & 1) * 8 + (lane >> 2);
#pragma unroll
        for (int j = 0; j < 4; ++j) {
            mv[m * 32 + owner * 4 + j] = cv[rr][j];
            mi[m * 32 + owner * 4 + j] = ci[rr][j];
        }
    }
    __syncthreads();
    if (t < 128) {
        float v8[8]; int i8[8]; float vmax = 3.4e38f; int smax = 0;
#pragma unroll
        for (int j = 0; j < 8; ++j) { v8[j] = 3.4e38f; i8[j] = 0; }
        const float* vr = mv + t * 32;
        const int*   ir = mi + t * 32;
#pragma unroll 4
        for (int j = 0; j < 32; ++j) {
            float s2 = vr[j];
            if (s2 < vmax) {
                v8[smax] = s2; i8[smax] = ir[j];
                vmax = v8[0]; smax = 0;
#pragma unroll
                for (int u = 1; u < 8; ++u)
                    if (v8[u] > vmax) { vmax = v8[u]; smax = u; }
            }
        }
        int p = b * HW + q0 + t;
        int4* dst = reinterpret_cast<int4*>(&g_cand[p * 8]);
        dst[0] = make_int4(i8[0], i8[1], i8[2], i8[3]);
        dst[1] = make_int4(i8[4], i8[5], i8[6], i8[7]);
    }
}

// ---------------------------------------------------------------------------
// Kernel 3: exact fp32 rescore of the 8 candidates (R2 rounding structure).
// ---------------------------------------------------------------------------
__global__ __launch_bounds__(256)
void vq_rescore(const float* __restrict__ z, const float* __restrict__ emb,
                float* __restrict__ fo, int* __restrict__ io) {
    __shared__ float zs[DIM * 32];            // [k][m], 32 KB
    const int t = threadIdx.x;
    const int p0 = blockIdx.x * 32;
    const int b = p0 >> 10, q0 = p0 & 1023;
    {
        int m = t & 31, kb = t >> 5;
        const float* zb = z + (size_t)b * DIM * HW + q0 + m;
#pragma unroll 4
        for (int i = 0; i < 32; ++i) {
            int k = kb + i * 8;
            zs[k * 32 + m] = zb[(size_t)k * HW];
        }
    }
    __syncthreads();

    const int m = t >> 3, c = t & 7, p = p0 + m;
    const int n = g_cand[p * 8 + c];
    const float Ap = g_A[p], Bn = __ldg(&g_bias[n]);
    const float4* e4 = reinterpret_cast<const float4*>(emb) + (size_t)n * 64;
    const float* zr = zs + m;
    float a0 = 0.f, a1 = 0.f, a2 = 0.f, a3 = 0.f;
#pragma unroll 8
    for (int k4 = 0; k4 < 64; ++k4) {
        float4 e = __ldg(e4 + k4);
        a0 = fmaf(zr[(k4 * 4 + 0) * 32], e.x, a0);
        a1 = fmaf(zr[(k4 * 4 + 1) * 32], e.y, a1);
        a2 = fmaf(zr[(k4 * 4 + 2) * 32], e.z, a2);
        a3 = fmaf(zr[(k4 * 4 + 3) * 32], e.w, a3);
    }
    float dot = (a0 + a1) + (a2 + a3);
    float d = __fadd_rn(__fadd_rn(Ap, Bn), -2.0f * dot);

    float bv = d; int bi = n;
#pragma unroll
    for (int off = 1; off < 8; off <<= 1) {
        float ov = __shfl_xor_sync(0xffffffffu, bv, off);
        int   oi = __shfl_xor_sync(0xffffffffu, bi, off);
        if (ov < bv || (ov == bv && oi < bi)) { bv = ov; bi = oi; }
    }
    if (c == 0) {
        g_idx[p] = bi;
        if (fo) fo[p] = (float)bi;
        if (io) io[p] = bi;
    }
}

// ---------------------------------------------------------------------------
// Kernel 4: z_q gather (coalesced writes).
// ---------------------------------------------------------------------------
__global__ void vq_gather(const float* __restrict__ emb, float* __restrict__ zq) {
    int p = blockIdx.x * blockDim.x + threadIdx.x;
    int b = p >> 10, q = p & 1023;
    int idx = g_idx[p];
    const float4* row = reinterpret_cast<const float4*>(emb + (size_t)idx * DIM);
    float* o = zq + (size_t)b * DIM * HW + q;
#pragma unroll 8
    for (int i = 0; i < DIM / 4; ++i) {
        float4 v = row[i];
        o[(size_t)(4 * i + 0) * HW] = v.x;
        o[(size_t)(4 * i + 1) * HW] = v.y;
        o[(size_t)(4 * i + 2) * HW] = v.z;
        o[(size_t)(4 * i + 3) * HW] = v.w;
    }
}

// ---------------------------------------------------------------------------
extern "C" void kernel_launch(void* const* d_in, const int* in_sizes, int n_in,
                              void* d_out, int out_size) {
    const float* z   = (const float*)d_in[0];
    const float* emb = (const float*)d_in[1];
    if (n_in >= 2 && in_sizes[0] == NCODE * DIM) {
        emb = (const float*)d_in[0]; z = (const float*)d_in[1];
    } else if (n_in >= 2 && in_sizes[1] == NCODE * DIM) {
        z = (const float*)d_in[0]; emb = (const float*)d_in[1];
    }

    const int ZQ = NPIX * DIM;
    float* fo = nullptr; int* io = nullptr; float* zq = nullptr;
    if (out_size == NPIX)      { io = (int*)d_out; }
    else if (out_size == ZQ)   { zq = (float*)d_out; }
    else                       { fo = (float*)d_out; zq = (float*)d_out + NPIX; }

    cudaFuncSetAttribute(vq_gemm, cudaFuncAttributeMaxDynamicSharedMemorySize, SM_TOT);

    vq_prep<<<32, 256>>>(emb);
    vq_gemm<<<NPIX / 128, 256, SM_TOT>>>(z);
    vq_rescore<<<NPIX / 32, 256>>>(z, emb, fo, io);
    if (zq) vq_gather<<<NPIX / 256, 256>>>(emb, zq);
}

// round 6
// speedup vs baseline: 2.0915x; 1.1095x over previous
#include <cuda_runtime.h>
#include <cuda_bf16.h>
#include <cstdint>

#define DIM    256
#define HW     1024
#define NPIX   65536
#define NCODE  1024
#define NCHUNK 8          // 1024 codes / 128 per chunk

// ------------------------- device globals (scratch) -------------------------
__device__ float         g_bias[NCODE];        // sum(e_n^2), fp64->fp32
__device__ float         g_A[NPIX];            // sum(z_p^2), fp64->fp32
__device__ int           g_cand[NPIX * 8];     // top-8 approx candidates
__device__ int           g_idx[NPIX];          // final indices
__device__ __nv_bfloat16 g_embh[NCODE * DIM];  // bf16 codebook

// ------------------------- PTX helpers (baseline ISA only) ------------------
__device__ __forceinline__ uint32_t smem_u32(const void* p) {
    uint32_t a;
    asm("{ .reg .u64 t; cvta.to.shared.u64 t, %1; cvt.u32.u64 %0, t; }"
        : "=r"(a) : "l"(p));
    return a;
}
__device__ __forceinline__ void ldsm4(uint32_t& r0, uint32_t& r1, uint32_t& r2,
                                      uint32_t& r3, uint32_t addr) {
    asm volatile("ldmatrix.sync.aligned.m8n8.x4.shared.b16 {%0,%1,%2,%3}, [%4];"
                 : "=r"(r0), "=r"(r1), "=r"(r2), "=r"(r3) : "r"(addr));
}
__device__ __forceinline__ void mma16816(float* d, const uint32_t* a,
                                         uint32_t b0, uint32_t b1) {
    asm volatile("mma.sync.aligned.m16n8k16.row.col.f32.bf16.bf16.f32 "
                 "{%0,%1,%2,%3}, {%4,%5,%6,%7}, {%8,%9}, {%0,%1,%2,%3};"
                 : "+f"(d[0]), "+f"(d[1]), "+f"(d[2]), "+f"(d[3])
                 : "r"(a[0]), "r"(a[1]), "r"(a[2]), "r"(a[3]), "r"(b0), "r"(b1));
}
#define CP_ASYNC16(dst, src) \
    asm volatile("cp.async.cg.shared.global [%0], [%1], 16;" :: "r"(dst), "l"(src))
#define CP_COMMIT() asm volatile("cp.async.commit_group;" ::: "memory")
#define CP_WAIT0()  asm volatile("cp.async.wait_group 0;" ::: "memory")

// ---------------------------------------------------------------------------
// Kernel 1 (prep): g_bias (fp64 exact) + bf16 codebook. grid=32, block=256.
// ---------------------------------------------------------------------------
__global__ void vq_prep(const float* __restrict__ emb) {
    int w   = blockIdx.x * 8 + (threadIdx.x >> 5);
    int lid = threadIdx.x & 31;
#pragma unroll
    for (int i = 0; i < 4; ++i) {
        int n = w * 4 + i;
        const float4* row = reinterpret_cast<const float4*>(emb + (size_t)n * DIM);
        float4 u = __ldg(row + lid * 2);
        float4 t = __ldg(row + lid * 2 + 1);
        double s = (double)u.x * u.x + (double)u.y * u.y + (double)u.z * u.z + (double)u.w * u.w
                 + (double)t.x * t.x + (double)t.y * t.y + (double)t.z * t.z + (double)t.w * t.w;
#pragma unroll
        for (int off = 16; off; off >>= 1) s += __shfl_xor_sync(0xffffffffu, s, off);
        if (lid == 0) g_bias[n] = (float)s;
        __nv_bfloat162 h0 = __floats2bfloat162_rn(u.x, u.y);
        __nv_bfloat162 h1 = __floats2bfloat162_rn(u.z, u.w);
        __nv_bfloat162 h2 = __floats2bfloat162_rn(t.x, t.y);
        __nv_bfloat162 h3 = __floats2bfloat162_rn(t.z, t.w);
        uint4 o;
        o.x = *reinterpret_cast<uint32_t*>(&h0); o.y = *reinterpret_cast<uint32_t*>(&h1);
        o.z = *reinterpret_cast<uint32_t*>(&h2); o.w = *reinterpret_cast<uint32_t*>(&h3);
        *reinterpret_cast<uint4*>(&g_embh[(size_t)n * DIM + lid * 8]) = o;
    }
}

// ---------------------------------------------------------------------------
// Kernel 2: bf16 mma.sync GEMM + top-8 shortlist.
//   A: 128 pixels x 256 dims, resident smem (XOR swizzle, 512B rows)
//   B: 128-code chunks, cp.async double buffer
//   warps: 4 (M) x 2 (N); each warp 32x64 via 2x8 m16n8k16 tiles
//   k-loop register-double-buffers ldmatrix fragments; top-k is branchless
//   compare-swap on register scalars (NO dynamic indexing -> no local mem).
// ---------------------------------------------------------------------------
#define SM_A   0
#define SM_B0  65536
#define SM_B1  131072
#define SM_AP  196608                 // double[256]
#define SM_TOT (196608 + 2048)

// smem byte offset for element (row, kchunk-of-8) in a 512B-row tile
#define ROWOFF(row, kc) ((row) * 512 + (((kc) ^ ((row) & 7)) << 4))

// prefetch one 128x256-bf16 chunk of the codebook into swizzled smem
__device__ __forceinline__ void prefetch_b(uint32_t bbuf, int nbase, int t) {
    const char* src = (const char*)g_embh + (size_t)nbase * 512;
#pragma unroll
    for (int i = 0; i < 16; ++i) {
        int idx = t + i * 256;       // 0..4095
        int n = idx >> 5, c = idx & 31;
        CP_ASYNC16(bbuf + ROWOFF(n, c), src + n * 512 + c * 16);
    }
}

extern __shared__ char smem[];

__global__ __launch_bounds__(256, 1)
void vq_gemm(const float* __restrict__ z) {
    const uint32_t sb = smem_u32(smem);
    const int t = threadIdx.x, wid = t >> 5, lane = t & 31;
    const int wm = wid & 3, wn = wid >> 2;
    const int b = blockIdx.x >> 3, q0 = (blockIdx.x & 7) * 128;

    // ---- stage A (fp32 -> bf16, swizzled) + fp64 ||z||^2 partials ----
    {
        const int m = t & 127, kh = t >> 7;
        const float* zb = z + (size_t)b * DIM * HW + q0 + m;
        double s = 0.0;
#pragma unroll 2
        for (int ch = 0; ch < 16; ++ch) {
            int k0 = kh * 128 + ch * 8;
            float vv[8];
#pragma unroll
            for (int j = 0; j < 8; ++j) {
                vv[j] = zb[(size_t)(k0 + j) * HW];
                s += (double)vv[j] * vv[j];
            }
            uint4 w;
            __nv_bfloat162 h0 = __floats2bfloat162_rn(vv[0], vv[1]);
            __nv_bfloat162 h1 = __floats2bfloat162_rn(vv[2], vv[3]);
            __nv_bfloat162 h2 = __floats2bfloat162_rn(vv[4], vv[5]);
            __nv_bfloat162 h3 = __floats2bfloat162_rn(vv[6], vv[7]);
            w.x = *reinterpret_cast<uint32_t*>(&h0); w.y = *reinterpret_cast<uint32_t*>(&h1);
            w.z = *reinterpret_cast<uint32_t*>(&h2); w.w = *reinterpret_cast<uint32_t*>(&h3);
            *reinterpret_cast<uint4*>(smem + SM_A + ROWOFF(m, k0 >> 3)) = w;
        }
        reinterpret_cast<double*>(smem + SM_AP)[t] = s;
    }

    // ---- prefetch B chunk 0 ----
    prefetch_b(sb + SM_B0, 0, t);
    CP_COMMIT();
    CP_WAIT0();
    __syncthreads();

    if (t < 128) {
        const double* ap = reinterpret_cast<const double*>(smem + SM_AP);
        g_A[b * HW + q0 + t] = (float)(ap[t] + ap[t + 128]);
    }

    // per-lane ldmatrix row geometry
    const int lrow  = (lane & 7) + ((lane >> 3) & 1) * 8;
    const int kcsel = lane >> 4;
    const int rowA0 = wm * 32 + lrow;
    const int rowB0 = wn * 64 + lrow;
    const uint32_t abase = sb + SM_A;

    // per-thread-row top-4 candidates, kept sorted ascending (registers only)
    float cv[4][4]; int ci[4][4];
#pragma unroll
    for (int r = 0; r < 4; ++r)
#pragma unroll
        for (int j = 0; j < 4; ++j) { cv[r][j] = 3.4e38f; ci[r][j] = 0; }

    for (int nt = 0; nt < NCHUNK; ++nt) {
        if (nt + 1 < NCHUNK) {
            prefetch_b(sb + (((nt + 1) & 1) ? SM_B1 : SM_B0), (nt + 1) * 128, t);
            CP_COMMIT();
        }
        const uint32_t bbuf = sb + ((nt & 1) ? SM_B1 : SM_B0);

        float acc[2][8][4];
#pragma unroll
        for (int mt = 0; mt < 2; ++mt)
#pragma unroll
            for (int n2 = 0; n2 < 8; ++n2)
#pragma unroll
                for (int j = 0; j < 4; ++j) acc[mt][n2][j] = 0.f;

        // register double-buffered fragments
        uint32_t afrag[2][2][4], bfrag[2][4][4];
#define LOAD_KS(ks, buf)                                                        \
        {                                                                       \
            const int kc_ = 2 * (ks) + kcsel;                                   \
            ldsm4(afrag[buf][0][0], afrag[buf][0][1], afrag[buf][0][2],         \
                  afrag[buf][0][3], abase + ROWOFF(rowA0, kc_));                \
            ldsm4(afrag[buf][1][0], afrag[buf][1][1], afrag[buf][1][2],         \
                  afrag[buf][1][3], abase + ROWOFF(rowA0 + 16, kc_));           \
            _Pragma("unroll")                                                   \
            for (int g_ = 0; g_ < 4; ++g_)                                      \
                ldsm4(bfrag[buf][g_][0], bfrag[buf][g_][1], bfrag[buf][g_][2],  \
                      bfrag[buf][g_][3], bbuf + ROWOFF(rowB0 + g_ * 16, kc_));  \
        }
        LOAD_KS(0, 0)
#pragma unroll
        for (int ks = 0; ks < 16; ++ks) {
            if (ks < 15) LOAD_KS(ks + 1, (ks + 1) & 1)
            const int cur = ks & 1;
#pragma unroll
            for (int g = 0; g < 4; ++g)
#pragma unroll
                for (int mt = 0; mt < 2; ++mt) {
                    mma16816(acc[mt][g * 2 + 0], afrag[cur][mt],
                             bfrag[cur][g][0], bfrag[cur][g][2]);
                    mma16816(acc[mt][g * 2 + 1], afrag[cur][mt],
                             bfrag[cur][g][1], bfrag[cur][g][3]);
                }
        }
#undef LOAD_KS

        // ---- epilogue: s = bias - 2*dot, branchless sorted top-4 insert ----
        const int nb0 = nt * 128 + wn * 64 + (lane & 3) * 2;
        float bias2[16];
#pragma unroll
        for (int n2 = 0; n2 < 8; ++n2) {
            bias2[n2 * 2 + 0] = __ldg(&g_bias[nb0 + n2 * 8 + 0]);
            bias2[n2 * 2 + 1] = __ldg(&g_bias[nb0 + n2 * 8 + 1]);
        }
#pragma unroll
        for (int mt = 0; mt < 2; ++mt)
#pragma unroll
            for (int h = 0; h < 2; ++h) {
                const int rr = mt * 2 + h;
#pragma unroll
                for (int n2 = 0; n2 < 8; ++n2)
#pragma unroll
                    for (int bb = 0; bb < 2; ++bb) {
                        float s2 = fmaf(-2.f, acc[mt][n2][h * 2 + bb], bias2[n2 * 2 + bb]);
                        if (s2 < cv[rr][3]) {          // rare slow path
                            cv[rr][3] = s2; ci[rr][3] = nb0 + n2 * 8 + bb;
#pragma unroll
                            for (int u = 3; u > 0; --u) {   // one bubble pass
                                bool sw = cv[rr][u] < cv[rr][u - 1];
                                float tv = cv[rr][u - 1]; int ti = ci[rr][u - 1];
                                cv[rr][u - 1] = sw ? cv[rr][u] : cv[rr][u - 1];
                                ci[rr][u - 1] = sw ? ci[rr][u] : ci[rr][u - 1];
                                cv[rr][u] = sw ? tv : cv[rr][u];
                                ci[rr][u] = sw ? ti : ci[rr][u];
                            }
                        }
                    }
            }

        CP_WAIT0();
        __syncthreads();
    }

    // ---- merge 32 candidates/pixel -> top-8 (reuse B0 region as scratch) ----
    float* mv = reinterpret_cast<float*>(smem + SM_B0);
    int*   mi = reinterpret_cast<int*>(smem + SM_B0 + 128 * 32 * 4);
    const int owner = wn * 4 + (lane & 3);
#pragma unroll
    for (int rr = 0; rr < 4; ++rr) {
        int m = wm * 32 + (rr >> 1) * 16 + (rr & 1) * 8 + (lane >> 2);
#pragma unroll
        for (int j = 0; j < 4; ++j) {
            mv[m * 32 + owner * 4 + j] = cv[rr][j];
            mi[m * 32 + owner * 4 + j] = ci[rr][j];
        }
    }
    __syncthreads();
    if (t < 128) {
        float v8[8]; int i8[8];
#pragma unroll
        for (int j = 0; j < 8; ++j) { v8[j] = 3.4e38f; i8[j] = 0; }
        const float* vr = mv + t * 32;
        const int*   ir = mi + t * 32;
#pragma unroll 4
        for (int j = 0; j < 32; ++j) {
            float s2 = vr[j];
            if (s2 < v8[7]) {
                v8[7] = s2; i8[7] = ir[j];
#pragma unroll
                for (int u = 7; u > 0; --u) {
                    bool sw = v8[u] < v8[u - 1];
                    float tv = v8[u - 1]; int ti = i8[u - 1];
                    v8[u - 1] = sw ? v8[u] : v8[u - 1];
                    i8[u - 1] = sw ? i8[u] : i8[u - 1];
                    v8[u] = sw ? tv : v8[u];
                    i8[u] = sw ? ti : i8[u];
                }
            }
        }
        int p = b * HW + q0 + t;
        int4* dst = reinterpret_cast<int4*>(&g_cand[p * 8]);
        dst[0] = make_int4(i8[0], i8[1], i8[2], i8[3]);
        dst[1] = make_int4(i8[4], i8[5], i8[6], i8[7]);
    }
}

// ---------------------------------------------------------------------------
// Kernel 3: exact fp32 rescore of the 8 candidates (R2 rounding structure).
// ---------------------------------------------------------------------------
__global__ __launch_bounds__(256)
void vq_rescore(const float* __restrict__ z, const float* __restrict__ emb,
                float* __restrict__ fo, int* __restrict__ io) {
    __shared__ float zs[DIM * 32];            // [k][m], 32 KB
    const int t = threadIdx.x;
    const int p0 = blockIdx.x * 32;
    const int b = p0 >> 10, q0 = p0 & 1023;
    {
        int m = t & 31, kb = t >> 5;
        const float* zb = z + (size_t)b * DIM * HW + q0 + m;
#pragma unroll 4
        for (int i = 0; i < 32; ++i) {
            int k = kb + i * 8;
            zs[k * 32 + m] = zb[(size_t)k * HW];
        }
    }
    __syncthreads();

    const int m = t >> 3, c = t & 7, p = p0 + m;
    const int n = g_cand[p * 8 + c];
    const float Ap = g_A[p], Bn = __ldg(&g_bias[n]);
    const float4* e4 = reinterpret_cast<const float4*>(emb) + (size_t)n * 64;
    const float* zr = zs + m;
    float a0 = 0.f, a1 = 0.f, a2 = 0.f, a3 = 0.f;
#pragma unroll 8
    for (int k4 = 0; k4 < 64; ++k4) {
        float4 e = __ldg(e4 + k4);
        a0 = fmaf(zr[(k4 * 4 + 0) * 32], e.x, a0);
        a1 = fmaf(zr[(k4 * 4 + 1) * 32], e.y, a1);
        a2 = fmaf(zr[(k4 * 4 + 2) * 32], e.z, a2);
        a3 = fmaf(zr[(k4 * 4 + 3) * 32], e.w, a3);
    }
    float dot = (a0 + a1) + (a2 + a3);
    float d = __fadd_rn(__fadd_rn(Ap, Bn), -2.0f * dot);

    float bv = d; int bi = n;
#pragma unroll
    for (int off = 1; off < 8; off <<= 1) {
        float ov = __shfl_xor_sync(0xffffffffu, bv, off);
        int   oi = __shfl_xor_sync(0xffffffffu, bi, off);
        if (ov < bv || (ov == bv && oi < bi)) { bv = ov; bi = oi; }
    }
    if (c == 0) {
        g_idx[p] = bi;
        if (fo) fo[p] = (float)bi;
        if (io) io[p] = bi;
    }
}

// ---------------------------------------------------------------------------
// Kernel 4: z_q gather (coalesced writes).
// ---------------------------------------------------------------------------
__global__ void vq_gather(const float* __restrict__ emb, float* __restrict__ zq) {
    int p = blockIdx.x * blockDim.x + threadIdx.x;
    int b = p >> 10, q = p & 1023;
    int idx = g_idx[p];
    const float4* row = reinterpret_cast<const float4*>(emb + (size_t)idx * DIM);
    float* o = zq + (size_t)b * DIM * HW + q;
#pragma unroll 8
    for (int i = 0; i < DIM / 4; ++i) {
        float4 v = row[i];
        o[(size_t)(4 * i + 0) * HW] = v.x;
        o[(size_t)(4 * i + 1) * HW] = v.y;
        o[(size_t)(4 * i + 2) * HW] = v.z;
        o[(size_t)(4 * i + 3) * HW] = v.w;
    }
}

// ---------------------------------------------------------------------------
extern "C" void kernel_launch(void* const* d_in, const int* in_sizes, int n_in,
                              void* d_out, int out_size) {
    const float* z   = (const float*)d_in[0];
    const float* emb = (const float*)d_in[1];
    if (n_in >= 2 && in_sizes[0] == NCODE * DIM) {
        emb = (const float*)d_in[0]; z = (const float*)d_in[1];
    } else if (n_in >= 2 && in_sizes[1] == NCODE * DIM) {
        z = (const float*)d_in[0]; emb = (const float*)d_in[1];
    }

    const int ZQ = NPIX * DIM;
    float* fo = nullptr; int* io = nullptr; float* zq = nullptr;
    if (out_size == NPIX)      { io = (int*)d_out; }
    else if (out_size == ZQ)   { zq = (float*)d_out; }
    else                       { fo = (float*)d_out; zq = (float*)d_out + NPIX; }

    cudaFuncSetAttribute(vq_gemm, cudaFuncAttributeMaxDynamicSharedMemorySize, SM_TOT);

    vq_prep<<<32, 256>>>(emb);
    vq_gemm<<<NPIX / 128, 256, SM_TOT>>>(z);
    vq_rescore<<<NPIX / 32, 256>>>(z, emb, fo, io);
    if (zq) vq_gather<<<NPIX / 256, 256>>>(emb, zq);
}

// round 10
// speedup vs baseline: 3.5650x; 1.7045x over previous
#include <cuda_runtime.h>
#include <cuda_bf16.h>
#include <cstdint>

#define DIM    256
#define HW     1024
#define NPIX   65536
#define NCODE  1024
#define NCHUNK 8          // 1024 codes / 128 per chunk

// ------------------------- device globals (scratch) -------------------------
__device__ float         g_bias[NCODE];        // sum(e_n^2), fp64->fp32
__device__ float         g_A[NPIX];            // sum(z_p^2), fp64->fp32
__device__ int           g_cand[NPIX * 4];     // top-4 approx candidates
__device__ int           g_idx[NPIX];          // final indices
__device__ __nv_bfloat16 g_embh[NCODE * DIM];  // bf16 codebook

// ------------------------- PTX helpers (baseline ISA only) ------------------
__device__ __forceinline__ uint32_t smem_u32(const void* p) {
    uint32_t a;
    asm("{ .reg .u64 t; cvta.to.shared.u64 t, %1; cvt.u32.u64 %0, t; }"
        : "=r"(a) : "l"(p));
    return a;
}
__device__ __forceinline__ void ldsm4(uint32_t& r0, uint32_t& r1, uint32_t& r2,
                                      uint32_t& r3, uint32_t addr) {
    asm volatile("ldmatrix.sync.aligned.m8n8.x4.shared.b16 {%0,%1,%2,%3}, [%4];"
                 : "=r"(r0), "=r"(r1), "=r"(r2), "=r"(r3) : "r"(addr));
}
__device__ __forceinline__ void mma16816(float* d, const uint32_t* a,
                                         uint32_t b0, uint32_t b1) {
    asm volatile("mma.sync.aligned.m16n8k16.row.col.f32.bf16.bf16.f32 "
                 "{%0,%1,%2,%3}, {%4,%5,%6,%7}, {%8,%9}, {%0,%1,%2,%3};"
                 : "+f"(d[0]), "+f"(d[1]), "+f"(d[2]), "+f"(d[3])
                 : "r"(a[0]), "r"(a[1]), "r"(a[2]), "r"(a[3]), "r"(b0), "r"(b1));
}
#define CP_ASYNC16(dst, src) \
    asm volatile("cp.async.cg.shared.global [%0], [%1], 16;" :: "r"(dst), "l"(src))
#define CP_COMMIT() asm volatile("cp.async.commit_group;" ::: "memory")
#define CP_WAIT0()  asm volatile("cp.async.wait_group 0;" ::: "memory")

// ---------------------------------------------------------------------------
// Kernel 1 (prep): g_bias (fp64 exact, bit-identical order to prior rounds)
// + bf16 codebook. grid=128, block=256: warp per codebook row.
// ---------------------------------------------------------------------------
__global__ void vq_prep(const float* __restrict__ emb) {
    int n   = blockIdx.x * 8 + (threadIdx.x >> 5);
    int lid = threadIdx.x & 31;
    const float4* row = reinterpret_cast<const float4*>(emb + (size_t)n * DIM);
    float4 u = __ldg(row + lid * 2);
    float4 t = __ldg(row + lid * 2 + 1);
    double s = (double)u.x * u.x + (double)u.y * u.y + (double)u.z * u.z + (double)u.w * u.w
             + (double)t.x * t.x + (double)t.y * t.y + (double)t.z * t.z + (double)t.w * t.w;
#pragma unroll
    for (int off = 16; off; off >>= 1) s += __shfl_xor_sync(0xffffffffu, s, off);
    if (lid == 0) g_bias[n] = (float)s;
    __nv_bfloat162 h0 = __floats2bfloat162_rn(u.x, u.y);
    __nv_bfloat162 h1 = __floats2bfloat162_rn(u.z, u.w);
    __nv_bfloat162 h2 = __floats2bfloat162_rn(t.x, t.y);
    __nv_bfloat162 h3 = __floats2bfloat162_rn(t.z, t.w);
    uint4 o;
    o.x = *reinterpret_cast<uint32_t*>(&h0); o.y = *reinterpret_cast<uint32_t*>(&h1);
    o.z = *reinterpret_cast<uint32_t*>(&h2); o.w = *reinterpret_cast<uint32_t*>(&h3);
    *reinterpret_cast<uint4*>(&g_embh[(size_t)n * DIM + lid * 8]) = o;
}

// ---------------------------------------------------------------------------
// Kernel 2: bf16 mma.sync GEMM + top-4 shortlist. 512 threads / 16 warps.
//   warps: 4 (M) x 4 (N); warp tile 32 pixels x 32 codes.
//   candidates packed u32: (dist_bits & ~1023) | code_id  (dists > 0).
// ---------------------------------------------------------------------------
#define SM_A   0
#define SM_B0  65536
#define SM_B1  131072
#define SM_AP  196608                 // double[512]
#define SM_AF  200704                 // float[128]
#define SM_TOT 201344

// smem byte offset for element (row, kchunk-of-8) in a 512B-row tile
#define ROWOFF(row, kc) ((row) * 512 + (((kc) ^ ((row) & 7)) << 4))

// prefetch one 128x256-bf16 chunk of the codebook (512 threads)
__device__ __forceinline__ void prefetch_b(uint32_t bbuf, int nbase, int t) {
    const char* src = (const char*)g_embh + (size_t)nbase * 512;
#pragma unroll
    for (int i = 0; i < 8; ++i) {
        int idx = t + i * 512;       // 0..4095
        int n = idx >> 5, c = idx & 31;
        CP_ASYNC16(bbuf + ROWOFF(n, c), src + n * 512 + c * 16);
    }
}

extern __shared__ char smem[];

__global__ __launch_bounds__(512, 1)
void vq_gemm(const float* __restrict__ z) {
    const uint32_t sb = smem_u32(smem);
    const int t = threadIdx.x, wid = t >> 5, lane = t & 31;
    const int wm = wid & 3, wn = wid >> 2;           // 4 x 4 warp grid
    const int b = blockIdx.x >> 3, q0 = (blockIdx.x & 7) * 128;

    // ---- stage A (fp32 -> bf16, swizzled) + fp64 ||z||^2 partials ----
    {
        const int m = t & 127, kq = t >> 7;          // kq 0..3 -> 64 dims each
        const float* zb = z + (size_t)b * DIM * HW + q0 + m;
        double s = 0.0;
#pragma unroll
        for (int ch = 0; ch < 8; ++ch) {
            int k0 = kq * 64 + ch * 8;
            float vv[8];
#pragma unroll
            for (int j = 0; j < 8; ++j) {
                vv[j] = zb[(size_t)(k0 + j) * HW];
                s += (double)vv[j] * vv[j];
            }
            uint4 w;
            __nv_bfloat162 h0 = __floats2bfloat162_rn(vv[0], vv[1]);
            __nv_bfloat162 h1 = __floats2bfloat162_rn(vv[2], vv[3]);
            __nv_bfloat162 h2 = __floats2bfloat162_rn(vv[4], vv[5]);
            __nv_bfloat162 h3 = __floats2bfloat162_rn(vv[6], vv[7]);
            w.x = *reinterpret_cast<uint32_t*>(&h0); w.y = *reinterpret_cast<uint32_t*>(&h1);
            w.z = *reinterpret_cast<uint32_t*>(&h2); w.w = *reinterpret_cast<uint32_t*>(&h3);
            *reinterpret_cast<uint4*>(smem + SM_A + ROWOFF(m, k0 >> 3)) = w;
        }
        reinterpret_cast<double*>(smem + SM_AP)[t] = s;
    }

    prefetch_b(sb + SM_B0, 0, t);
    CP_COMMIT();
    CP_WAIT0();
    __syncthreads();

    if (t < 128) {
        const double* ap = reinterpret_cast<const double*>(smem + SM_AP);
        float Af = (float)(ap[t] + ap[t + 128] + ap[t + 256] + ap[t + 384]);
        g_A[b * HW + q0 + t] = Af;
        reinterpret_cast<float*>(smem + SM_AF)[t] = Af;
    }
    __syncthreads();

    // per-lane ldmatrix geometry
    const int lrow  = (lane & 7) + ((lane >> 3) & 1) * 8;
    const int kcsel = lane >> 4;
    const int rowA0 = wm * 32 + lrow;
    const int rowB0 = wn * 32 + lrow;
    const uint32_t abase = sb + SM_A;

    // this thread's 4 pixel rows and their ||z||^2
    float Arow[4];
#pragma unroll
    for (int rr = 0; rr < 4; ++rr) {
        int m = wm * 32 + (rr >> 1) * 16 + (rr & 1) * 8 + (lane >> 2);
        Arow[rr] = reinterpret_cast<const float*>(smem + SM_AF)[m];
    }

    // per-row top-4 packed candidates, sorted ascending
    uint32_t cv[4][4];
#pragma unroll
    for (int r = 0; r < 4; ++r)
#pragma unroll
        for (int j = 0; j < 4; ++j) cv[r][j] = 0xFFFFFFFFu;

    for (int nt = 0; nt < NCHUNK; ++nt) {
        if (nt + 1 < NCHUNK) {
            prefetch_b(sb + (((nt + 1) & 1) ? SM_B1 : SM_B0), (nt + 1) * 128, t);
            CP_COMMIT();
        }
        const uint32_t bbuf = sb + ((nt & 1) ? SM_B1 : SM_B0);

        float acc[2][4][4];
#pragma unroll
        for (int mt = 0; mt < 2; ++mt)
#pragma unroll
            for (int n2 = 0; n2 < 4; ++n2)
#pragma unroll
                for (int j = 0; j < 4; ++j) acc[mt][n2][j] = 0.f;

        uint32_t afrag[2][2][4], bfrag[2][2][4];
#define LOAD_KS(ks, buf)                                                        \
        {                                                                       \
            const int kc_ = 2 * (ks) + kcsel;                                   \
            ldsm4(afrag[buf][0][0], afrag[buf][0][1], afrag[buf][0][2],         \
                  afrag[buf][0][3], abase + ROWOFF(rowA0, kc_));                \
            ldsm4(afrag[buf][1][0], afrag[buf][1][1], afrag[buf][1][2],         \
                  afrag[buf][1][3], abase + ROWOFF(rowA0 + 16, kc_));           \
            ldsm4(bfrag[buf][0][0], bfrag[buf][0][1], bfrag[buf][0][2],         \
                  bfrag[buf][0][3], bbuf + ROWOFF(rowB0, kc_));                 \
            ldsm4(bfrag[buf][1][0], bfrag[buf][1][1], bfrag[buf][1][2],         \
                  bfrag[buf][1][3], bbuf + ROWOFF(rowB0 + 16, kc_));            \
        }
        LOAD_KS(0, 0)
#pragma unroll
        for (int ks = 0; ks < 16; ++ks) {
            if (ks < 15) LOAD_KS(ks + 1, (ks + 1) & 1)
            const int cur = ks & 1;
#pragma unroll
            for (int g = 0; g < 2; ++g)
#pragma unroll
                for (int mt = 0; mt < 2; ++mt) {
                    mma16816(acc[mt][g * 2 + 0], afrag[cur][mt],
                             bfrag[cur][g][0], bfrag[cur][g][2]);
                    mma16816(acc[mt][g * 2 + 1], afrag[cur][mt],
                             bfrag[cur][g][1], bfrag[cur][g][3]);
                }
        }
#undef LOAD_KS

        // ---- epilogue: pack (dist, id) and top-4 insert per row ----
        const int nb0 = nt * 128 + wn * 32 + (lane & 3) * 2;
        float bias2[8];
#pragma unroll
        for (int n2 = 0; n2 < 4; ++n2) {
            bias2[n2 * 2 + 0] = __ldg(&g_bias[nb0 + n2 * 8 + 0]);
            bias2[n2 * 2 + 1] = __ldg(&g_bias[nb0 + n2 * 8 + 1]);
        }
#pragma unroll
        for (int mt = 0; mt < 2; ++mt)
#pragma unroll
            for (int h = 0; h < 2; ++h) {
                const int rr = mt * 2 + h;
#pragma unroll
                for (int n2 = 0; n2 < 4; ++n2)
#pragma unroll
                    for (int bb = 0; bb < 2; ++bb) {
                        float s2 = fmaf(-2.f, acc[mt][n2][h * 2 + bb],
                                        bias2[n2 * 2 + bb]) + Arow[rr];
                        uint32_t u = (__float_as_uint(s2) & 0xFFFFFC00u)
                                   | (uint32_t)(nb0 + n2 * 8 + bb);
                        if (u < cv[rr][3]) {
                            cv[rr][3] = u;
#pragma unroll
                            for (int v = 3; v > 0; --v) {
                                bool sw = cv[rr][v] < cv[rr][v - 1];
                                uint32_t tv = cv[rr][v - 1];
                                cv[rr][v - 1] = sw ? cv[rr][v] : cv[rr][v - 1];
                                cv[rr][v]     = sw ? tv : cv[rr][v];
                            }
                        }
                    }
            }

        CP_WAIT0();
        __syncthreads();
    }

    // ---- merge 64 packed candidates/pixel -> top-4 (scratch in B0, pad 65) --
    uint32_t* mv = reinterpret_cast<uint32_t*>(smem + SM_B0);
    const int owner = wn * 4 + (lane & 3);           // 0..15
#pragma unroll
    for (int rr = 0; rr < 4; ++rr) {
        int m = wm * 32 + (rr >> 1) * 16 + (rr & 1) * 8 + (lane >> 2);
#pragma unroll
        for (int j = 0; j < 4; ++j)
            mv[m * 65 + owner * 4 + j] = cv[rr][j];
    }
    __syncthreads();
    if (t < 128) {
        uint32_t v4[4];
#pragma unroll
        for (int j = 0; j < 4; ++j) v4[j] = 0xFFFFFFFFu;
        const uint32_t* vr = mv + t * 65;
#pragma unroll 4
        for (int j = 0; j < 64; ++j) {
            uint32_t u = vr[j];
            if (u < v4[3]) {
                v4[3] = u;
#pragma unroll
                for (int v = 3; v > 0; --v) {
                    bool sw = v4[v] < v4[v - 1];
                    uint32_t tv = v4[v - 1];
                    v4[v - 1] = sw ? v4[v] : v4[v - 1];
                    v4[v]     = sw ? tv : v4[v];
                }
            }
        }
        int p = b * HW + q0 + t;
        *reinterpret_cast<int4*>(&g_cand[p * 4]) =
            make_int4(v4[0] & 1023, v4[1] & 1023, v4[2] & 1023, v4[3] & 1023);
    }
}

// ---------------------------------------------------------------------------
// Kernel 3: exact fp32 rescore of 4 candidates. Per-thread serial 4-chain
// dot with the EXACT arithmetic order proven in rounds 2/5/6 (this order is
// part of the correctness contract -- do not change).
// Block = 256 threads = 64 pixels x 4 candidate-threads; grid = NPIX/64.
// ---------------------------------------------------------------------------
__global__ __launch_bounds__(256)
void vq_rescore(const float* __restrict__ z, const float* __restrict__ emb,
                float* __restrict__ fo, int* __restrict__ io) {
    float* zs = reinterpret_cast<float*>(smem);   // [k][m] pitch 64, 64 KB
    const int t = threadIdx.x;
    const int p0 = blockIdx.x * 64;
    const int b = p0 >> 10, q0 = p0 & 1023;
    {
        int m = t & 63, kb = t >> 6;              // kb 0..3
        const float* zb = z + (size_t)b * DIM * HW + q0 + m;
#pragma unroll 8
        for (int i = 0; i < 64; ++i) {
            int k = kb + i * 4;
            zs[k * 64 + m] = zb[(size_t)k * HW];
        }
    }
    __syncthreads();

    const int m = t >> 2, c = t & 3, p = p0 + m;
    const int n = g_cand[p * 4 + c];
    const float Ap = g_A[p], Bn = __ldg(&g_bias[n]);
    const float4* e4 = reinterpret_cast<const float4*>(emb) + (size_t)n * 64;
    const float* zr = zs + m;
    float a0 = 0.f, a1 = 0.f, a2 = 0.f, a3 = 0.f;
#pragma unroll 8
    for (int k4 = 0; k4 < 64; ++k4) {
        float4 e = __ldg(e4 + k4);
        a0 = fmaf(zr[(k4 * 4 + 0) * 64], e.x, a0);
        a1 = fmaf(zr[(k4 * 4 + 1) * 64], e.y, a1);
        a2 = fmaf(zr[(k4 * 4 + 2) * 64], e.z, a2);
        a3 = fmaf(zr[(k4 * 4 + 3) * 64], e.w, a3);
    }
    float dot = (a0 + a1) + (a2 + a3);
    float d = __fadd_rn(__fadd_rn(Ap, Bn), -2.0f * dot);

    float bv = d; int bi = n;
#pragma unroll
    for (int off = 1; off < 4; off <<= 1) {
        float ov = __shfl_xor_sync(0xffffffffu, bv, off);
        int   oi = __shfl_xor_sync(0xffffffffu, bi, off);
        if (ov < bv || (ov == bv && oi < bi)) { bv = ov; bi = oi; }
    }
    if (c == 0) {
        g_idx[p] = bi;
        if (fo) fo[p] = (float)bi;
        if (io) io[p] = bi;
    }
}

// ---------------------------------------------------------------------------
// Kernel 4: z_q gather via smem transpose -- coalesced reads AND writes.
// Block = 256 threads, 32 pixels; grid = NPIX/32 = 2048.
// ---------------------------------------------------------------------------
__global__ __launch_bounds__(256)
void vq_gather(const float* __restrict__ emb, float* __restrict__ zq) {
    __shared__ float zs[32 * 257];
    __shared__ int ids[32];
    const int t = threadIdx.x;
    const int p0 = blockIdx.x * 32;
    const int b = p0 >> 10, q0 = p0 & 1023;
    if (t < 32) ids[t] = g_idx[p0 + t];
    __syncthreads();
    {   // stage 32 emb rows, 8 threads per row, float4 reads
        int r = t >> 3, cc = t & 7;
        const float4* src = reinterpret_cast<const float4*>(emb)
                          + (size_t)ids[r] * 64;
#pragma unroll
        for (int i = 0; i < 8; ++i) {
            float4 v = __ldg(src + cc + i * 8);
            int d = (cc + i * 8) * 4;
            zs[r * 257 + d + 0] = v.x;
            zs[r * 257 + d + 1] = v.y;
            zs[r * 257 + d + 2] = v.z;
            zs[r * 257 + d + 3] = v.w;
        }
    }
    __syncthreads();
    {   // write out[b, d, q0+q]: warp-constant d -> fully coalesced stores
        int q = t & 31, w = t >> 5;
        float* o = zq + (size_t)b * DIM * HW + q0 + q;
#pragma unroll 8
        for (int i = 0; i < 32; ++i) {
            int d = w * 32 + i;
            o[(size_t)d * HW] = zs[q * 257 + d];
        }
    }
}

// ---------------------------------------------------------------------------
extern "C" void kernel_launch(void* const* d_in, const int* in_sizes, int n_in,
                              void* d_out, int out_size) {
    const float* z   = (const float*)d_in[0];
    const float* emb = (const float*)d_in[1];
    if (n_in >= 2 && in_sizes[0] == NCODE * DIM) {
        emb = (const float*)d_in[0]; z = (const float*)d_in[1];
    } else if (n_in >= 2 && in_sizes[1] == NCODE * DIM) {
        z = (const float*)d_in[0]; emb = (const float*)d_in[1];
    }

    const int ZQ = NPIX * DIM;
    float* fo = nullptr; int* io = nullptr; float* zq = nullptr;
    if (out_size == NPIX)      { io = (int*)d_out; }
    else if (out_size == ZQ)   { zq = (float*)d_out; }
    else                       { fo = (float*)d_out; zq = (float*)d_out + NPIX; }

    cudaFuncSetAttribute(vq_gemm, cudaFuncAttributeMaxDynamicSharedMemorySize, SM_TOT);
    cudaFuncSetAttribute(vq_rescore, cudaFuncAttributeMaxDynamicSharedMemorySize, 65536);

    vq_prep<<<128, 256>>>(emb);
    vq_gemm<<<NPIX / 128, 512, SM_TOT>>>(z);
    vq_rescore<<<NPIX / 64, 256, 65536>>>(z, emb, fo, io);
    if (zq) vq_gather<<<NPIX / 32, 256>>>(emb, zq);
}